// round 8
// baseline (speedup 1.0000x reference)
#include <cuda_runtime.h>

#define ZD   16      // x feature dim
#define NJ   160     // basis(10) x sh(16) flattened, grouped by l
#define NF   2560    // output features per graph = ZD * NJ
#define NT   32      // nodes per tile
#define NTH  256
#define SBS  27      // sh(16)+basis(10) padded row stride

typedef unsigned long long u64;

__device__ __forceinline__ u64 pack2(float a, float b) {
    u64 r;
    asm("mov.b64 %0, {%1, %2};" : "=l"(r) : "f"(a), "f"(b));
    return r;
}
__device__ __forceinline__ void fma2(u64& d, u64 a, u64 b) {
    asm("fma.rn.f32x2 %0, %1, %2, %0;" : "+l"(d) : "l"(a), "l"(b));
}

__device__ __forceinline__ int lb_any(const int* __restrict__ b32, int n, int key, bool is64) {
    int lo = 0, hi = n;
    while (lo < hi) {
        int mid = (lo + hi) >> 1;
        int v = is64 ? b32[2 * mid] : b32[mid];  // LE low word == value (0..1023)
        if (v < key) lo = mid + 1; else hi = mid;
    }
    return lo;
}

__global__ __launch_bounds__(NTH, 3)
void yfeat_kernel(const float* __restrict__ x,
                  const float* __restrict__ pos,
                  const int*   __restrict__ batch32,
                  float* __restrict__ out,
                  int n_nodes)
{
    __shared__ __align__(16) float x_s[NT * ZD];
    __shared__ float sb_s[NT * SBS];                 // [0..15]=sh, [16..25]=basis
    __shared__ __align__(16) float v_s[NT * NJ];     // v[j]=basis[b(j)]*sh[m(j)]; reused as acc_s
    __shared__ unsigned int idx_s[NJ];               // packed byte offsets: (boff<<16)|soff
    __shared__ int s_range[2];

    const int t = threadIdx.x;
    const int g = blockIdx.x;

    // int64 vs int32 batch detection (sorted, max id ~1023: int64 -> high word 0)
    const bool is64 = (batch32[n_nodes - 1] == 0);

    if (t < 2) s_range[t] = lb_any(batch32, n_nodes, g + t, is64);

    // once-per-kernel j -> (basis, sh) byte-offset table
    if (t >= 64 && t < 64 + NJ) {
        const int j = t - 64;
        int b, s;
        if (j < 10)       { b = j;                       s = 0; }
        else if (j < 40)  { int jj = j - 10; b = jj / 3; s = 1 + (jj - 3 * b); }
        else if (j < 90)  { int jj = j - 40; b = jj / 5; s = 4 + (jj - 5 * b); }
        else              { int jj = j - 90; b = jj / 7; s = 9 + (jj - 7 * b); }
        idx_s[j] = (((unsigned)(16 + b) * 4u) << 16) | ((unsigned)s * 4u);
    }
    __syncthreads();

    const int start = s_range[0];
    const int end   = s_range[1];
    const int cnt   = end - start;

    const int gi  = t >> 6;           // node-split group 0..3
    const int sub = t & 63;
    const int z4  = sub >> 4;         // 0..3 -> z block of 4
    const int jc  = sub & 15;         // 0..15
    const int j0  = jc * 10;          // never straddles l-blocks (10/40/90 are mult of 10)

    u64 acc[20];                      // [zz*5+k] = packed (j0+2k, j0+2k+1) for z=z4*4+zz
#pragma unroll
    for (int k = 0; k < 20; ++k) acc[k] = 0ull;

    for (int base = start; base < end; base += NT) {
        const int tc = min(NT, end - base);
        __syncthreads();  // prior tile consumers done before overwriting smem

        // ---- phase A: stage x (coalesced) + sh (32 lanes) + basis (5 lanes/node) ----
        for (int i = t; i < tc * ZD; i += NTH) x_s[i] = x[(size_t)base * ZD + i];

        if (t < tc) {
            const float px = pos[(size_t)(base + t) * 3 + 0];
            const float py = pos[(size_t)(base + t) * 3 + 1];
            const float pz = pos[(size_t)(base + t) * 3 + 2];
            const float rinv = rsqrtf(px * px + py * py + pz * pz);
            const float ux = px * rinv, uy = py * rinv, uz = pz * rinv;
            float* sb = &sb_s[t * SBS];

            const float s3  = 1.7320508075688772f;
            const float s5  = 2.23606797749979f;
            const float s7  = 2.6457513110645907f;
            const float s15 = 3.872983346207417f;
            const float c42  = 1.0801234497346435f;   // sqrt(42)/6
            const float c168 = 1.620185174601965f;    // sqrt(168)/8

            const float X2 = ux * ux, Y2 = uy * uy, Z2 = uz * uz;
            const float x2z2 = X2 + Z2;
            const float sh4 = s15 * ux * uz;
            const float sh8 = 0.5f * s15 * (Z2 - X2);

            sb[0]  = 1.0f;
            sb[1]  = s3 * ux;  sb[2] = s3 * uy;  sb[3] = s3 * uz;
            sb[4]  = sh4;
            sb[5]  = s15 * ux * uy;
            sb[6]  = s5 * (Y2 - 0.5f * x2z2);
            sb[7]  = s15 * uy * uz;
            sb[8]  = sh8;
            sb[9]  = c42 * (sh4 * uz + sh8 * ux);
            sb[10] = s7 * sh4 * uy;
            sb[11] = c168 * (4.0f * Y2 - x2z2) * ux;
            sb[12] = 0.5f * s7 * uy * (2.0f * Y2 - 3.0f * x2z2);
            sb[13] = c168 * uz * (4.0f * Y2 - x2z2);
            sb[14] = s7 * sh8 * uy;
            sb[15] = c42 * (sh8 * uz - sh4 * ux);
        }

        {   // basis: 5 threads per node, 2 elems each (MUFU spread over 5 warps)
            const int bt = t - 32;
            if (bt >= 0 && bt < tc * 5) {
                const unsigned node = (unsigned)bt / 5u;
                const int i0 = 2 * (bt - 5 * (int)node);
                const float px = pos[(size_t)(base + node) * 3 + 0];
                const float py = pos[(size_t)(base + node) * 3 + 1];
                const float pz = pos[(size_t)(base + node) * 3 + 2];
                const float r2 = px * px + py * py + pz * pz;
                const float d  = r2 * rsqrtf(r2);
                const float dd = 1.1f * d;                  // d/step, step = 10/11
                const float C = 1.14136f * 7.389056098930650f * 3.1622776601683795f;
#pragma unroll
                for (int q = 0; q < 2; ++q) {
                    const int i = i0 + q;
                    const float u1 = dd - (float)i;         // diff+1
                    const float u2 = (float)(i + 2) - dd;   // 1-diff
                    float v = 0.0f;
                    if (u1 > 0.0f && u2 > 0.0f)             // exp(-1/u1)*exp(-1/u2) fused
                        v = C * __expf(-(__fdividef(1.0f, u1) + __fdividef(1.0f, u2)));
                    sb_s[node * SBS + 16 + i] = v;
                }
            }
        }
        __syncthreads();

        // ---- phase B: v-build, warp-per-node, no divisions ----
        {
            const int w = t >> 5, lid = t & 31;
            for (int n = w; n < tc; n += 8) {
                const char* sbn = (const char*)&sb_s[n * SBS];
                float* vn = &v_s[n * NJ];
#pragma unroll
                for (int i = 0; i < 5; ++i) {
                    const int j = lid + 32 * i;
                    const unsigned ix = idx_s[j];
                    const float bv = *(const float*)(sbn + (ix >> 16));
                    const float sv = *(const float*)(sbn + (ix & 0xffffu));
                    vn[j] = bv * sv;
                }
            }
        }
        __syncthreads();

        // ---- phase C: hot loop — packed f32x2 rank-1 accumulation ----
        for (int n = gi; n < tc; n += 4) {
            const float4 xv = *(const float4*)&x_s[n * ZD + z4 * 4];
            const u64* vr = (const u64*)&v_s[n * NJ + j0];   // 8B aligned: 640n+40jc
            const u64 xp0 = pack2(xv.x, xv.x);
            const u64 xp1 = pack2(xv.y, xv.y);
            const u64 xp2 = pack2(xv.z, xv.z);
            const u64 xp3 = pack2(xv.w, xv.w);
#pragma unroll
            for (int k = 0; k < 5; ++k) {
                const u64 vv = vr[k];
                fma2(acc[k],      xp0, vv);
                fma2(acc[5 + k],  xp1, vv);
                fma2(acc[10 + k], xp2, vv);
                fma2(acc[15 + k], xp3, vv);
            }
        }
    }

    // ---- cross-group reduction in smem (reuse v_s), then coalesced mean write ----
    float* acc_s = v_s;   // 2560 <= NT*NJ, safe: all hot-loop reads are done
    for (int gp = 0; gp < 4; ++gp) {
        __syncthreads();
        if (gi == gp) {
#pragma unroll
            for (int zz = 0; zz < 4; ++zz) {
                const int z = z4 * 4 + zz;
                int f0;
                if (j0 < 10)      f0 = z * 10 + j0;
                else if (j0 < 40) f0 = 160  + z * 30 + (j0 - 10);
                else if (j0 < 90) f0 = 640  + z * 50 + (j0 - 40);
                else              f0 = 1440 + z * 70 + (j0 - 90);
#pragma unroll
                for (int k = 0; k < 5; ++k) {
                    float2 val = *(float2*)&acc[zz * 5 + k];
                    float2* dst = (float2*)&acc_s[f0 + 2 * k];   // f0 even -> 8B aligned
                    if (gp == 0) *dst = val;
                    else { float2 c = *dst; c.x += val.x; c.y += val.y; *dst = c; }
                }
            }
        }
    }
    __syncthreads();

    const float inv = 1.0f / (float)max(cnt, 1);
    float* og = out + (size_t)g * NF;
    for (int f = t; f < NF; f += NTH) og[f] = acc_s[f] * inv;
}

extern "C" void kernel_launch(void* const* d_in, const int* in_sizes, int n_in,
                              void* d_out, int out_size) {
    const float* x     = (const float*)d_in[0];
    const float* pos   = (const float*)d_in[1];
    const int*   batch = (const int*)d_in[2];   // int32 or int64; detected on device
    float* out = (float*)d_out;
    const int n_nodes = in_sizes[2];
    const int n_graphs = out_size / NF;         // 1024
    yfeat_kernel<<<n_graphs, NTH>>>(x, pos, batch, out, n_nodes);
}

// round 9
// speedup vs baseline: 1.5128x; 1.5128x over previous
#include <cuda_runtime.h>

#define ZD   16      // x feature dim
#define NJ   160     // basis(10) x sh(16) flattened, grouped by l
#define NF   2560    // output features per graph = ZD * NJ
#define NT   32      // nodes per tile
#define NTH  256
#define SBS  27      // sh(16)+basis(10) padded row stride

typedef unsigned long long u64;

__device__ __forceinline__ u64 pack2(float a, float b) {
    u64 r;
    asm("mov.b64 %0, {%1, %2};" : "=l"(r) : "f"(a), "f"(b));
    return r;
}
__device__ __forceinline__ void fma2(u64& d, u64 a, u64 b) {
    asm("fma.rn.f32x2 %0, %1, %2, %0;" : "+l"(d) : "l"(a), "l"(b));
}

__device__ __forceinline__ int lb_any(const int* __restrict__ b32, int n, int key, bool is64) {
    int lo = 0, hi = n;
    while (lo < hi) {
        int mid = (lo + hi) >> 1;
        int v = is64 ? b32[2 * mid] : b32[mid];  // LE low word == value (0..1023)
        if (v < key) lo = mid + 1; else hi = mid;
    }
    return lo;
}

__global__ __launch_bounds__(NTH, 3)
void yfeat_kernel(const float* __restrict__ x,
                  const float* __restrict__ pos,
                  const int*   __restrict__ batch32,
                  float* __restrict__ out,
                  int n_nodes)
{
    __shared__ __align__(16) float x_s[NT * ZD];
    __shared__ float sb_s[NT * SBS];                 // [0..15]=sh, [16..25]=basis
    __shared__ __align__(16) float v_s[NT * NJ];     // v[j]=basis[b(j)]*sh[m(j)]; reused as acc_s
    __shared__ unsigned int idx_s[NJ];               // packed byte offsets: (boff<<16)|soff
    __shared__ int s_range[2];

    const int t = threadIdx.x;
    const int g = blockIdx.x;

    // int64 vs int32 batch detection (sorted, max id ~1023: int64 -> high word 0)
    const bool is64 = (batch32[n_nodes - 1] == 0);

    if (t < 2) s_range[t] = lb_any(batch32, n_nodes, g + t, is64);

    // once-per-kernel j -> (basis, sh) byte-offset table
    if (t >= 64 && t < 64 + NJ) {
        const int j = t - 64;
        int b, s;
        if (j < 10)       { b = j;                       s = 0; }
        else if (j < 40)  { int jj = j - 10; b = jj / 3; s = 1 + (jj - 3 * b); }
        else if (j < 90)  { int jj = j - 40; b = jj / 5; s = 4 + (jj - 5 * b); }
        else              { int jj = j - 90; b = jj / 7; s = 9 + (jj - 7 * b); }
        idx_s[j] = (((unsigned)(16 + b) * 4u) << 16) | ((unsigned)s * 4u);
    }
    __syncthreads();

    const int start = s_range[0];
    const int end   = s_range[1];
    const int cnt   = end - start;

    const int gi  = t >> 6;           // node-split group 0..3
    const int sub = t & 63;
    const int z4  = sub >> 4;         // 0..3 -> z block of 4
    const int jc  = sub & 15;         // 0..15
    const int j0  = jc * 10;          // never straddles l-blocks (10/40/90 are mult of 10)

    u64 acc[20];                      // [zz*5+k] = packed (j0+2k, j0+2k+1) for z=z4*4+zz
#pragma unroll
    for (int k = 0; k < 20; ++k) acc[k] = 0ull;

    for (int base = start; base < end; base += NT) {
        const int tc = min(NT, end - base);
        __syncthreads();  // prior tile consumers done before overwriting smem

        // ---- phase A: stage x (coalesced) + sh (32 lanes) + basis (5 lanes/node) ----
        for (int i = t; i < tc * ZD; i += NTH) x_s[i] = x[(size_t)base * ZD + i];

        if (t < tc) {
            const float px = pos[(size_t)(base + t) * 3 + 0];
            const float py = pos[(size_t)(base + t) * 3 + 1];
            const float pz = pos[(size_t)(base + t) * 3 + 2];
            const float rinv = rsqrtf(px * px + py * py + pz * pz);
            const float ux = px * rinv, uy = py * rinv, uz = pz * rinv;
            float* sb = &sb_s[t * SBS];

            const float s3  = 1.7320508075688772f;
            const float s5  = 2.23606797749979f;
            const float s7  = 2.6457513110645907f;
            const float s15 = 3.872983346207417f;
            const float c42  = 1.0801234497346435f;   // sqrt(42)/6
            const float c168 = 1.620185174601965f;    // sqrt(168)/8

            const float X2 = ux * ux, Y2 = uy * uy, Z2 = uz * uz;
            const float x2z2 = X2 + Z2;
            const float sh4 = s15 * ux * uz;
            const float sh8 = 0.5f * s15 * (Z2 - X2);

            sb[0]  = 1.0f;
            sb[1]  = s3 * ux;  sb[2] = s3 * uy;  sb[3] = s3 * uz;
            sb[4]  = sh4;
            sb[5]  = s15 * ux * uy;
            sb[6]  = s5 * (Y2 - 0.5f * x2z2);
            sb[7]  = s15 * uy * uz;
            sb[8]  = sh8;
            sb[9]  = c42 * (sh4 * uz + sh8 * ux);
            sb[10] = s7 * sh4 * uy;
            sb[11] = c168 * (4.0f * Y2 - x2z2) * ux;
            sb[12] = 0.5f * s7 * uy * (2.0f * Y2 - 3.0f * x2z2);
            sb[13] = c168 * uz * (4.0f * Y2 - x2z2);
            sb[14] = s7 * sh8 * uy;
            sb[15] = c42 * (sh8 * uz - sh4 * ux);
        }

        {   // basis: 5 threads per node, 2 elems each (MUFU spread over 5 warps)
            const int bt = t - 32;
            if (bt >= 0 && bt < tc * 5) {
                const unsigned node = (unsigned)bt / 5u;
                const int i0 = 2 * (bt - 5 * (int)node);
                const float px = pos[(size_t)(base + node) * 3 + 0];
                const float py = pos[(size_t)(base + node) * 3 + 1];
                const float pz = pos[(size_t)(base + node) * 3 + 2];
                const float r2 = px * px + py * py + pz * pz;
                const float d  = r2 * rsqrtf(r2);
                const float dd = 1.1f * d;                  // d/step, step = 10/11
                const float C = 1.14136f * 7.389056098930650f * 3.1622776601683795f;
#pragma unroll
                for (int q = 0; q < 2; ++q) {
                    const int i = i0 + q;
                    const float u1 = dd - (float)i;         // diff+1
                    const float u2 = (float)(i + 2) - dd;   // 1-diff
                    float v = 0.0f;
                    if (u1 > 0.0f && u2 > 0.0f)             // exp(-1/u1)*exp(-1/u2) fused
                        v = C * __expf(-(__fdividef(1.0f, u1) + __fdividef(1.0f, u2)));
                    sb_s[node * SBS + 16 + i] = v;
                }
            }
        }
        __syncthreads();

        // ---- phase B: v-build, warp-per-node, no divisions ----
        {
            const int w = t >> 5, lid = t & 31;
            for (int n = w; n < tc; n += 8) {
                const char* sbn = (const char*)&sb_s[n * SBS];
                float* vn = &v_s[n * NJ];
#pragma unroll
                for (int i = 0; i < 5; ++i) {
                    const int j = lid + 32 * i;
                    const unsigned ix = idx_s[j];
                    const float bv = *(const float*)(sbn + (ix >> 16));
                    const float sv = *(const float*)(sbn + (ix & 0xffffu));
                    vn[j] = bv * sv;
                }
            }
        }
        __syncthreads();

        // ---- phase C: hot loop — packed f32x2 rank-1 accumulation ----
        for (int n = gi; n < tc; n += 4) {
            const float4 xv = *(const float4*)&x_s[n * ZD + z4 * 4];
            const u64* vr = (const u64*)&v_s[n * NJ + j0];   // 8B aligned: 640n+40jc
            const u64 xp0 = pack2(xv.x, xv.x);
            const u64 xp1 = pack2(xv.y, xv.y);
            const u64 xp2 = pack2(xv.z, xv.z);
            const u64 xp3 = pack2(xv.w, xv.w);
#pragma unroll
            for (int k = 0; k < 5; ++k) {
                const u64 vv = vr[k];
                fma2(acc[k],      xp0, vv);
                fma2(acc[5 + k],  xp1, vv);
                fma2(acc[10 + k], xp2, vv);
                fma2(acc[15 + k], xp3, vv);
            }
        }
    }

    // ---- cross-group reduction in smem (reuse v_s), then coalesced mean write ----
    float* acc_s = v_s;   // 2560 <= NT*NJ, safe: all hot-loop reads are done
    for (int gp = 0; gp < 4; ++gp) {
        __syncthreads();
        if (gi == gp) {
#pragma unroll
            for (int zz = 0; zz < 4; ++zz) {
                const int z = z4 * 4 + zz;
                int f0;
                if (j0 < 10)      f0 = z * 10 + j0;
                else if (j0 < 40) f0 = 160  + z * 30 + (j0 - 10);
                else if (j0 < 90) f0 = 640  + z * 50 + (j0 - 40);
                else              f0 = 1440 + z * 70 + (j0 - 90);
#pragma unroll
                for (int k = 0; k < 5; ++k) {
                    float2 val = *(float2*)&acc[zz * 5 + k];
                    float2* dst = (float2*)&acc_s[f0 + 2 * k];   // f0 even -> 8B aligned
                    if (gp == 0) *dst = val;
                    else { float2 c = *dst; c.x += val.x; c.y += val.y; *dst = c; }
                }
            }
        }
    }
    __syncthreads();

    const float inv = 1.0f / (float)max(cnt, 1);
    float* og = out + (size_t)g * NF;
    for (int f = t; f < NF; f += NTH) og[f] = acc_s[f] * inv;
}

extern "C" void kernel_launch(void* const* d_in, const int* in_sizes, int n_in,
                              void* d_out, int out_size) {
    const float* x     = (const float*)d_in[0];
    const float* pos   = (const float*)d_in[1];
    const int*   batch = (const int*)d_in[2];   // int32 or int64; detected on device
    float* out = (float*)d_out;
    const int n_nodes = in_sizes[2];
    const int n_graphs = out_size / NF;         // 1024
    yfeat_kernel<<<n_graphs, NTH>>>(x, pos, batch, out, n_nodes);
}